// round 6
// baseline (speedup 1.0000x reference)
#include <cuda_runtime.h>
#include <math.h>

#define B_  8
#define S_  1024
#define D_  1024
#define H_  16
#define DK_ 64

// Scratch (device globals: no allocation allowed in kernel_launch)
__device__ float g_q[B_*S_*D_];
__device__ float g_k[B_*S_*D_];
__device__ float g_v[B_*S_*D_];
__device__ float g_att[B_*S_*D_];
__device__ float g_cq[B_*S_*D_];   // tf32-rounded inputs
__device__ float g_ck[B_*S_*D_];
__device__ float g_cv[B_*S_*D_];
__device__ float g_wq[D_*D_];      // tf32-rounded weights
__device__ float g_wk[D_*D_];
__device__ float g_wv[D_*D_];
__device__ float g_wo[D_*D_];

__device__ __forceinline__ unsigned f2tf32(float x) {
    unsigned u;
    asm("cvt.rna.tf32.f32 %0, %1;" : "=r"(u) : "f"(x));
    return u;
}

// Branchless exp2 for z <= 0, FFMA/ALU only (no MUFU).
__device__ __forceinline__ float exp2c(float z) {
    z = fmaxf(z, -126.0f);
    const float magic = 12582912.0f;           // 1.5*2^23
    float r = z + magic;
    int   n = __float_as_int(r) - __float_as_int(magic);
    float f = z - (r - magic);                 // f in [-0.5, 0.5]
    float c = 0.0013333558f;
    c = fmaf(c, f, 0.0096181291f);
    c = fmaf(c, f, 0.0555041087f);
    c = fmaf(c, f, 0.2402265069f);
    c = fmaf(c, f, 0.6931471806f);
    c = fmaf(c, f, 1.0f);
    return c * __int_as_float((n + 127) << 23);
}

// ---------------------------------------------------------------------------
// Elementwise tf32 pre-round (fp32 -> tf32 bit pattern stored as float)
// ---------------------------------------------------------------------------
__global__ void __launch_bounds__(256) cvt_tf32_kernel(
    const float4* __restrict__ in, float4* __restrict__ out, int n4)
{
    const int i = blockIdx.x * 256 + threadIdx.x;
    if (i < n4) {
        float4 v = in[i];
        v.x = __uint_as_float(f2tf32(v.x));
        v.y = __uint_as_float(f2tf32(v.y));
        v.z = __uint_as_float(f2tf32(v.z));
        v.w = __uint_as_float(f2tf32(v.w));
        out[i] = v;
    }
}

// ---------------------------------------------------------------------------
// tf32 tensor-core GEMM, raw-bit operands (pre-rounded): C = A @ W^T + bias
// OUTTF: round outputs to tf32 bits (for tensors feeding later mmas).
// ---------------------------------------------------------------------------
#define TILE_F 4608   // 128*36 floats per smem tile

template<int OUTTF>
__global__ void __launch_bounds__(256, 2) gemm_tf32_raw(
    const float* __restrict__ A, const float* __restrict__ W,
    const float* __restrict__ bias, float* __restrict__ C,
    int M, int N, int K)
{
    extern __shared__ float sm[];
    const int tid  = threadIdx.x;
    const int warp = tid >> 5, lane = tid & 31;
    const int wm = warp & 1, wn = warp >> 1;
    const int g = lane >> 2, t = lane & 3;
    const int m0 = blockIdx.y << 7, n0 = blockIdx.x << 7;

    const int lrow = tid >> 3;
    const int lcol = (tid & 7) << 2;

    float acc[4][4][4];
#pragma unroll
    for (int i = 0; i < 4; i++)
#pragma unroll
        for (int j = 0; j < 4; j++)
#pragma unroll
            for (int c = 0; c < 4; c++) acc[i][j][c] = 0.f;

    const int NCHUNK = K >> 5;

    {
        float* sA = sm;
        float* sW = sm + TILE_F;
#pragma unroll
        for (int l = 0; l < 4; l++) {
            const int row = lrow + (l << 5);
            unsigned da = (unsigned)__cvta_generic_to_shared(&sA[row * 36 + lcol]);
            unsigned dw = (unsigned)__cvta_generic_to_shared(&sW[row * 36 + lcol]);
            const float* ga = A + (size_t)(m0 + row) * K + lcol;
            const float* gw = W + (size_t)(n0 + row) * K + lcol;
            asm volatile("cp.async.cg.shared.global [%0], [%1], 16;" :: "r"(da), "l"(ga));
            asm volatile("cp.async.cg.shared.global [%0], [%1], 16;" :: "r"(dw), "l"(gw));
        }
        asm volatile("cp.async.commit_group;");
    }

    for (int kc = 0; kc < NCHUNK; kc++) {
        if (kc + 1 < NCHUNK) {
            const int k0 = (kc + 1) << 5;
            float* sA = sm + ((kc + 1) & 1) * (2 * TILE_F);
            float* sW = sA + TILE_F;
#pragma unroll
            for (int l = 0; l < 4; l++) {
                const int row = lrow + (l << 5);
                unsigned da = (unsigned)__cvta_generic_to_shared(&sA[row * 36 + lcol]);
                unsigned dw = (unsigned)__cvta_generic_to_shared(&sW[row * 36 + lcol]);
                const float* ga = A + (size_t)(m0 + row) * K + k0 + lcol;
                const float* gw = W + (size_t)(n0 + row) * K + k0 + lcol;
                asm volatile("cp.async.cg.shared.global [%0], [%1], 16;" :: "r"(da), "l"(ga));
                asm volatile("cp.async.cg.shared.global [%0], [%1], 16;" :: "r"(dw), "l"(gw));
            }
            asm volatile("cp.async.commit_group;");
            asm volatile("cp.async.wait_group 1;");
        } else {
            asm volatile("cp.async.wait_group 0;");
        }
        __syncthreads();

        const float* sA = sm + (kc & 1) * (2 * TILE_F);
        const float* sW = sA + TILE_F;

#pragma unroll
        for (int ks = 0; ks < 4; ks++) {
            const int kk = ks << 3;
            unsigned af[4][4], bf[4][2];
#pragma unroll
            for (int ma = 0; ma < 4; ma++) {
                const int r0 = wm * 64 + ma * 16 + g;
                af[ma][0] = __float_as_uint(sA[r0 * 36 + kk + t]);
                af[ma][1] = __float_as_uint(sA[(r0 + 8) * 36 + kk + t]);
                af[ma][2] = __float_as_uint(sA[r0 * 36 + kk + t + 4]);
                af[ma][3] = __float_as_uint(sA[(r0 + 8) * 36 + kk + t + 4]);
            }
#pragma unroll
            for (int na = 0; na < 4; na++) {
                const int rn = wn * 32 + na * 8 + g;
                bf[na][0] = __float_as_uint(sW[rn * 36 + kk + t]);
                bf[na][1] = __float_as_uint(sW[rn * 36 + kk + t + 4]);
            }
#pragma unroll
            for (int ma = 0; ma < 4; ma++)
#pragma unroll
                for (int na = 0; na < 4; na++) {
                    asm volatile(
                        "mma.sync.aligned.m16n8k8.row.col.f32.tf32.tf32.f32 "
                        "{%0,%1,%2,%3}, {%4,%5,%6,%7}, {%8,%9}, {%0,%1,%2,%3};"
                        : "+f"(acc[ma][na][0]), "+f"(acc[ma][na][1]),
                          "+f"(acc[ma][na][2]), "+f"(acc[ma][na][3])
                        : "r"(af[ma][0]), "r"(af[ma][1]), "r"(af[ma][2]), "r"(af[ma][3]),
                          "r"(bf[na][0]), "r"(bf[na][1]));
                }
        }
        __syncthreads();
    }

#pragma unroll
    for (int na = 0; na < 4; na++) {
        const int col = n0 + wn * 32 + na * 8 + 2 * t;
        const float bx = bias[col], by = bias[col + 1];
#pragma unroll
        for (int ma = 0; ma < 4; ma++) {
            const int row0 = m0 + wm * 64 + ma * 16 + g;
            float2 r;
            r.x = acc[ma][na][0] + bx; r.y = acc[ma][na][1] + by;
            if (OUTTF) {
                r.x = __uint_as_float(f2tf32(r.x));
                r.y = __uint_as_float(f2tf32(r.y));
            }
            *(float2*)(C + (size_t)row0 * N + col) = r;
            r.x = acc[ma][na][2] + bx; r.y = acc[ma][na][3] + by;
            if (OUTTF) {
                r.x = __uint_as_float(f2tf32(r.x));
                r.y = __uint_as_float(f2tf32(r.y));
            }
            *(float2*)(C + (size_t)(row0 + 8) * N + col) = r;
        }
    }
}

// ---------------------------------------------------------------------------
// Tensor-core flash attention, Q/K/V as tf32 bit patterns, O written as tf32
// bits. 256 thr = 8 warps, 128 q-rows, k-tile 64, 2 CTAs/SM target.
// ---------------------------------------------------------------------------
#define KSTR 68
#define VSTR 72
#define KT (64 * KSTR)
#define VT (64 * VSTR)
#define PSOFF (2 * KT + 2 * VT)
#define FLASH_SMEM ((PSOFF + 128 * 68) * 4)   // 106496 bytes

__global__ void __launch_bounds__(256, 2) flash_tc(
    const float* __restrict__ Q, const float* __restrict__ Kp,
    const float* __restrict__ V, const int* __restrict__ mask,
    float* __restrict__ O)
{
    extern __shared__ float smf[];
    float* KsB = smf;                 // [2][64][68]
    float* VsB = smf + 2 * KT;        // [2][64][72]
    float* Ps  = smf + PSOFF;         // [128][68]

    const int tid  = threadIdx.x;
    const int w    = tid >> 5, lane = tid & 31;
    const int g    = lane >> 2, t = lane & 3;
    const int q0   = (int)blockIdx.x << 7;
    const int bh   = blockIdx.y;
    const int b    = bh >> 4, h = bh & 15;
    const float SCL = 0.125f * 1.4426950408889634f;

    {
#pragma unroll
        for (int l = 0; l < 4; l++) {
            const int f = tid + (l << 8);
            const int row = f >> 4, c4 = (f & 15) << 2;
            const size_t src = (size_t)(b * S_ + row) * D_ + h * DK_ + c4;
            unsigned dk = (unsigned)__cvta_generic_to_shared(&KsB[row * KSTR + c4]);
            unsigned dv = (unsigned)__cvta_generic_to_shared(&VsB[row * VSTR + c4]);
            asm volatile("cp.async.cg.shared.global [%0], [%1], 16;" :: "r"(dk), "l"(Kp + src));
            asm volatile("cp.async.cg.shared.global [%0], [%1], 16;" :: "r"(dv), "l"(V + src));
        }
        asm volatile("cp.async.commit_group;");
    }

#pragma unroll
    for (int l = 0; l < 8; l++) {
        const int f = tid + (l << 8);
        const int row = f >> 4, c4 = (f & 15) << 2;
        *(float4*)&Ps[row * 68 + c4] =
            *(const float4*)(Q + (size_t)(b * S_ + q0 + row) * D_ + h * DK_ + c4);
    }
    __syncthreads();

    const int r0 = w * 16 + g;
    unsigned qf[8][4];
#pragma unroll
    for (int kf = 0; kf < 8; kf++) {
        const int kk = kf << 3;
        qf[kf][0] = __float_as_uint(Ps[r0 * 68 + kk + t]);
        qf[kf][1] = __float_as_uint(Ps[(r0 + 8) * 68 + kk + t]);
        qf[kf][2] = __float_as_uint(Ps[r0 * 68 + kk + t + 4]);
        qf[kf][3] = __float_as_uint(Ps[(r0 + 8) * 68 + kk + t + 4]);
    }

    float m_r[2] = {-INFINITY, -INFINITY};
    float l_r[2] = {0.f, 0.f};
    float accO[8][4];
#pragma unroll
    for (int na = 0; na < 8; na++)
#pragma unroll
        for (int c = 0; c < 4; c++) accO[na][c] = 0.f;

    const int NT = S_ / 64;
    for (int kt = 0; kt < NT; kt++) {
        __syncthreads();

        if (kt + 1 < NT) {
            const int k1 = (kt + 1) << 6;
            float* dK = KsB + ((kt + 1) & 1) * KT;
            float* dV = VsB + ((kt + 1) & 1) * VT;
#pragma unroll
            for (int l = 0; l < 4; l++) {
                const int f = tid + (l << 8);
                const int row = f >> 4, c4 = (f & 15) << 2;
                const size_t src = (size_t)(b * S_ + k1 + row) * D_ + h * DK_ + c4;
                unsigned dk = (unsigned)__cvta_generic_to_shared(&dK[row * KSTR + c4]);
                unsigned dv = (unsigned)__cvta_generic_to_shared(&dV[row * VSTR + c4]);
                asm volatile("cp.async.cg.shared.global [%0], [%1], 16;" :: "r"(dk), "l"(Kp + src));
                asm volatile("cp.async.cg.shared.global [%0], [%1], 16;" :: "r"(dv), "l"(V + src));
            }
            asm volatile("cp.async.commit_group;");
            asm volatile("cp.async.wait_group 1;");
        } else {
            asm volatile("cp.async.wait_group 0;");
        }
        __syncthreads();

        const float* Ks = KsB + (kt & 1) * KT;
        const float* Vs = VsB + (kt & 1) * VT;
        const int k0 = kt << 6;

        // ---- S = Q K^T ----
        float sa[8][4];
#pragma unroll
        for (int na = 0; na < 8; na++)
#pragma unroll
            for (int c = 0; c < 4; c++) sa[na][c] = 0.f;

#pragma unroll
        for (int kf = 0; kf < 8; kf++) {
            const int kk = kf << 3;
            unsigned bk[8][2];
#pragma unroll
            for (int na = 0; na < 8; na++) {
                bk[na][0] = __float_as_uint(Ks[(8 * na + g) * KSTR + kk + t]);
                bk[na][1] = __float_as_uint(Ks[(8 * na + g) * KSTR + kk + t + 4]);
            }
#pragma unroll
            for (int na = 0; na < 8; na++) {
                asm volatile(
                    "mma.sync.aligned.m16n8k8.row.col.f32.tf32.tf32.f32 "
                    "{%0,%1,%2,%3}, {%4,%5,%6,%7}, {%8,%9}, {%0,%1,%2,%3};"
                    : "+f"(sa[na][0]), "+f"(sa[na][1]), "+f"(sa[na][2]), "+f"(sa[na][3])
                    : "r"(qf[kf][0]), "r"(qf[kf][1]), "r"(qf[kf][2]), "r"(qf[kf][3]),
                      "r"(bk[na][0]), "r"(bk[na][1]));
            }
        }

        // ---- masked online softmax, register-lean ----
#pragma unroll
        for (int rh = 0; rh < 2; rh++) {
            const int ci = rh << 1;
            const int* mrow = mask + (size_t)(b * S_ + q0 + w * 16 + g + 8 * rh) * S_
                                   + k0 + 2 * t;
            float mt = -INFINITY;
#pragma unroll
            for (int na = 0; na < 8; na++) {
                const int2 mk = *(const int2*)(mrow + 8 * na);
                const float y0 = mk.x ? sa[na][ci]     * SCL : -INFINITY;
                const float y1 = mk.y ? sa[na][ci + 1] * SCL : -INFINITY;
                sa[na][ci] = y0; sa[na][ci + 1] = y1;
                mt = fmaxf(mt, fmaxf(y0, y1));
            }
            mt = fmaxf(mt, __shfl_xor_sync(0xffffffffu, mt, 1));
            mt = fmaxf(mt, __shfl_xor_sync(0xffffffffu, mt, 2));
            const float mn = fmaxf(m_r[rh], mt);

            const float alpha = exp2c(m_r[rh] - mn);
            float rs = 0.f;
            float* prow = Ps + (w * 16 + g + 8 * rh) * 68 + 2 * t;
#pragma unroll
            for (int na = 0; na < 8; na++) {
                const float y0 = sa[na][ci], y1 = sa[na][ci + 1];
                const float p0 = (y0 > -INFINITY) ? exp2c(y0 - mn) : 0.f;
                const float p1 = (y1 > -INFINITY) ? exp2c(y1 - mn) : 0.f;
                rs += p0 + p1;
                float2 st;
                st.x = __uint_as_float(f2tf32(p0));
                st.y = __uint_as_float(f2tf32(p1));
                *(float2*)(prow + 8 * na) = st;
            }
            rs += __shfl_xor_sync(0xffffffffu, rs, 1);
            rs += __shfl_xor_sync(0xffffffffu, rs, 2);

            l_r[rh] = alpha * l_r[rh] + rs;
            m_r[rh] = mn;
#pragma unroll
            for (int na = 0; na < 8; na++) {
                accO[na][ci]     *= alpha;
                accO[na][ci + 1] *= alpha;
            }
        }
        __syncthreads();

        // ---- O += P V ----
#pragma unroll
        for (int kf = 0; kf < 8; kf++) {
            const int kk = kf << 3;
            unsigned pa[4];
            pa[0] = __float_as_uint(Ps[r0 * 68 + kk + t]);
            pa[1] = __float_as_uint(Ps[(r0 + 8) * 68 + kk + t]);
            pa[2] = __float_as_uint(Ps[r0 * 68 + kk + t + 4]);
            pa[3] = __float_as_uint(Ps[(r0 + 8) * 68 + kk + t + 4]);
            unsigned bv[8][2];
#pragma unroll
            for (int na = 0; na < 8; na++) {
                bv[na][0] = __float_as_uint(Vs[(kk + t) * VSTR + 8 * na + g]);
                bv[na][1] = __float_as_uint(Vs[(kk + t + 4) * VSTR + 8 * na + g]);
            }
#pragma unroll
            for (int na = 0; na < 8; na++) {
                asm volatile(
                    "mma.sync.aligned.m16n8k8.row.col.f32.tf32.tf32.f32 "
                    "{%0,%1,%2,%3}, {%4,%5,%6,%7}, {%8,%9}, {%0,%1,%2,%3};"
                    : "+f"(accO[na][0]), "+f"(accO[na][1]), "+f"(accO[na][2]), "+f"(accO[na][3])
                    : "r"(pa[0]), "r"(pa[1]), "r"(pa[2]), "r"(pa[3]),
                      "r"(bv[na][0]), "r"(bv[na][1]));
            }
        }
    }

    // ---- normalize (tf32-rounded), stage, coalesced write ----
    __syncthreads();
#pragma unroll
    for (int rh = 0; rh < 2; rh++) {
        const int ci = rh << 1;
        const float inv = (l_r[rh] > 0.f) ? __frcp_rn(l_r[rh]) : 0.f;
        float* prow = Ps + (w * 16 + g + 8 * rh) * 68 + 2 * t;
#pragma unroll
        for (int na = 0; na < 8; na++) {
            float2 r;
            r.x = __uint_as_float(f2tf32(accO[na][ci]     * inv));
            r.y = __uint_as_float(f2tf32(accO[na][ci + 1] * inv));
            *(float2*)(prow + 8 * na) = r;
        }
    }
    __syncthreads();
#pragma unroll
    for (int l = 0; l < 8; l++) {
        const int f = tid + (l << 8);
        const int row = f >> 4, c4 = (f & 15) << 2;
        *(float4*)(O + (size_t)(b * S_ + q0 + row) * D_ + h * DK_ + c4) =
            *(float4*)&Ps[row * 68 + c4];
    }
}

// ---------------------------------------------------------------------------
extern "C" void kernel_launch(void* const* d_in, const int* in_sizes, int n_in,
                              void* d_out, int out_size) {
    (void)in_sizes; (void)n_in; (void)out_size;
    const float* query = (const float*)d_in[0];
    const float* key   = (const float*)d_in[1];
    const float* value = (const float*)d_in[2];
    const int*   msk   = (const int*)  d_in[3];
    const float* wq = (const float*)d_in[4];  const float* bq = (const float*)d_in[5];
    const float* wk = (const float*)d_in[6];  const float* bk = (const float*)d_in[7];
    const float* wv = (const float*)d_in[8];  const float* bv = (const float*)d_in[9];
    const float* wo = (const float*)d_in[10]; const float* bo = (const float*)d_in[11];
    float* out = (float*)d_out;

    float *gq, *gk, *gv, *ga, *cq, *ck, *cv, *pwq, *pwk, *pwv, *pwo;
    cudaGetSymbolAddress((void**)&gq, g_q);
    cudaGetSymbolAddress((void**)&gk, g_k);
    cudaGetSymbolAddress((void**)&gv, g_v);
    cudaGetSymbolAddress((void**)&ga, g_att);
    cudaGetSymbolAddress((void**)&cq, g_cq);
    cudaGetSymbolAddress((void**)&ck, g_ck);
    cudaGetSymbolAddress((void**)&cv, g_cv);
    cudaGetSymbolAddress((void**)&pwq, g_wq);
    cudaGetSymbolAddress((void**)&pwk, g_wk);
    cudaGetSymbolAddress((void**)&pwv, g_wv);
    cudaGetSymbolAddress((void**)&pwo, g_wo);

    const int M = B_ * S_;
    const dim3 gGrid(D_ / 128, M / 128);
    const int gemm_smem = 4 * TILE_F * sizeof(float);  // 73728 B

    static bool attr_set = false;
    if (!attr_set) {
        cudaFuncSetAttribute(gemm_tf32_raw<1>, cudaFuncAttributeMaxDynamicSharedMemorySize, gemm_smem);
        cudaFuncSetAttribute(gemm_tf32_raw<0>, cudaFuncAttributeMaxDynamicSharedMemorySize, gemm_smem);
        cudaFuncSetAttribute(flash_tc, cudaFuncAttributeMaxDynamicSharedMemorySize, FLASH_SMEM);
        attr_set = true;
    }

    const int n4_in = B_ * S_ * D_ / 4;    // 2097152
    const int n4_w  = D_ * D_ / 4;         // 262144
    cvt_tf32_kernel<<<n4_in / 256, 256>>>((const float4*)query, (float4*)cq, n4_in);
    cvt_tf32_kernel<<<n4_in / 256, 256>>>((const float4*)key,   (float4*)ck, n4_in);
    cvt_tf32_kernel<<<n4_in / 256, 256>>>((const float4*)value, (float4*)cv, n4_in);
    cvt_tf32_kernel<<<n4_w  / 256, 256>>>((const float4*)wq, (float4*)pwq, n4_w);
    cvt_tf32_kernel<<<n4_w  / 256, 256>>>((const float4*)wk, (float4*)pwk, n4_w);
    cvt_tf32_kernel<<<n4_w  / 256, 256>>>((const float4*)wv, (float4*)pwv, n4_w);
    cvt_tf32_kernel<<<n4_w  / 256, 256>>>((const float4*)wo, (float4*)pwo, n4_w);

    gemm_tf32_raw<1><<<gGrid, 256, gemm_smem>>>(cq, pwq, bq, gq, M, D_, D_);
    gemm_tf32_raw<1><<<gGrid, 256, gemm_smem>>>(ck, pwk, bk, gk, M, D_, D_);
    gemm_tf32_raw<1><<<gGrid, 256, gemm_smem>>>(cv, pwv, bv, gv, M, D_, D_);

    flash_tc<<<dim3(S_ / 128, B_ * H_), 256, FLASH_SMEM>>>(gq, gk, gv, msk, ga);

    gemm_tf32_raw<0><<<gGrid, 256, gemm_smem>>>(ga, pwo, bo, out, M, D_, D_);
}